// round 2
// baseline (speedup 1.0000x reference)
#include <cuda_runtime.h>
#include <cuda_bf16.h>

#define N_NODES 100000
#define KNN 16
#define D 128

// Scratch (static device arrays — no allocation in kernel_launch)
__device__ float g_P[(size_t)N_NODES * D];   // feature @ Wm
__device__ float g_S[(size_t)N_NODES * D];   // feature @ Ws
__device__ int   g_idx[N_NODES * KNN];       // normalized int32 indices
__device__ int   g_idx_is64;

// ---------------------------------------------------------------------------
// Index dtype detection: genuine int64 indices are all < N_NODES; an int32
// buffer viewed as int64 packs two indices (lo + hi*2^32) and is ~never
// in range. Reads only 4KB — safe under both layouts (int32 buffer is 6.4MB).
// ---------------------------------------------------------------------------
__global__ void pgnn_detect_idx_kernel(const unsigned long long* __restrict__ buf)
{
    if (threadIdx.x == 0 && blockIdx.x == 0) {
        int bad = 0;
        for (int i = 0; i < 512; i++) {
            if (buf[i] >= (unsigned long long)N_NODES) bad++;
        }
        g_idx_is64 = (bad == 0) ? 1 : 0;
    }
}

__global__ __launch_bounds__(256) void pgnn_convert_idx_kernel(const void* __restrict__ buf)
{
    int i = blockIdx.x * blockDim.x + threadIdx.x;
    if (i >= N_NODES * KNN) return;
    long long v;
    if (g_idx_is64) v = ((const long long*)buf)[i];
    else            v = (long long)((const int*)buf)[i];
    if (v < 0) v = 0;
    if (v >= N_NODES) v = N_NODES - 1;
    g_idx[i] = (int)v;
}

// ---------------------------------------------------------------------------
// Kernel 1: fused GEMM  C[N,256] = feature[N,128] @ [Wm | Ws]
//   cols 0..127   -> g_P  (Wm = W_hidden rows 0..127)
//   cols 128..255 -> g_S  (Ws = W_hidden rows 128..255)
// 256 threads/block, tile 64 rows x 256 cols, 8x8 microtile per thread.
// Whole W (128KB) + A tile (32KB) in dynamic smem (160KB, opt-in).
// ---------------------------------------------------------------------------
#define TILE_ROWS 64
#define CHUNKS 4

extern __shared__ float smem_dyn[];

__global__ __launch_bounds__(256, 1) void pgnn_gemm_kernel(
    const float* __restrict__ A,   // feature [N,128]
    const float* __restrict__ W)   // W_hidden [256,128]
{
    float* Bsm = smem_dyn;              // [128][256]
    float* Asm = smem_dyn + 128 * 256;  // [64][128]

    const int tid  = threadIdx.x;
    const int warp = tid >> 5;
    const int lane = tid & 31;

    // ---- load W into Bsm: Bsm[d][j<128]=Wm[d][j], Bsm[d][128+j]=Ws[d][j] ----
    #pragma unroll
    for (int i = 0; i < 16; i++) {
        int e = (i * 256 + tid) * 4;          // float index within 128x128 half
        int d = e >> 7, j = e & 127;
        float4 vm = *(const float4*)(W + e);
        float4 vs = *(const float4*)(W + 16384 + e);
        *(float4*)(Bsm + d * 256 + j)       = vm;
        *(float4*)(Bsm + d * 256 + 128 + j) = vs;
    }

    for (int ch = 0; ch < CHUNKS; ch++) {
        long long base = ((long long)blockIdx.x * CHUNKS + ch) * TILE_ROWS;
        if (base >= N_NODES) break;
        __syncthreads();   // covers Bsm (first iter) and Asm reuse (later iters)

        // ---- load A tile (64 x 128) ----
        #pragma unroll
        for (int i = 0; i < 8; i++) {
            int e = (i * 256 + tid) * 4;
            int r = e >> 7, c = e & 127;
            long long grow = base + r;
            float4 v = make_float4(0.f, 0.f, 0.f, 0.f);
            if (grow < N_NODES) v = *(const float4*)(A + grow * D + c);
            *(float4*)(Asm + r * D + c) = v;
        }
        __syncthreads();

        float acc[8][8];
        #pragma unroll
        for (int r = 0; r < 8; r++)
            #pragma unroll
            for (int q = 0; q < 8; q++) acc[r][q] = 0.f;

        const int colP = lane * 4;
        const int rowb = warp * 8;

        #pragma unroll 4
        for (int d = 0; d < D; d++) {
            float4 w0 = *(const float4*)(Bsm + d * 256 + colP);
            float4 w1 = *(const float4*)(Bsm + d * 256 + 128 + colP);
            float a[8];
            #pragma unroll
            for (int r = 0; r < 8; r++) a[r] = Asm[(rowb + r) * D + d];
            #pragma unroll
            for (int r = 0; r < 8; r++) {
                acc[r][0] = fmaf(a[r], w0.x, acc[r][0]);
                acc[r][1] = fmaf(a[r], w0.y, acc[r][1]);
                acc[r][2] = fmaf(a[r], w0.z, acc[r][2]);
                acc[r][3] = fmaf(a[r], w0.w, acc[r][3]);
                acc[r][4] = fmaf(a[r], w1.x, acc[r][4]);
                acc[r][5] = fmaf(a[r], w1.y, acc[r][5]);
                acc[r][6] = fmaf(a[r], w1.z, acc[r][6]);
                acc[r][7] = fmaf(a[r], w1.w, acc[r][7]);
            }
        }

        #pragma unroll
        for (int r = 0; r < 8; r++) {
            long long grow = base + rowb + r;
            if (grow < N_NODES) {
                float4 vp = make_float4(acc[r][0], acc[r][1], acc[r][2], acc[r][3]);
                float4 vs = make_float4(acc[r][4], acc[r][5], acc[r][6], acc[r][7]);
                *(float4*)(g_P + grow * D + colP) = vp;
                *(float4*)(g_S + grow * D + colP) = vs;
            }
        }
    }
}

// ---------------------------------------------------------------------------
// Kernel 2: per-node gather + relu + reductions.
// hidden[n,k,t] = relu(dm[n,k] * P[idx[n,k]][t] + S[n][t] + b[t])
// out_position[n,k]  = sum_t hidden * w_out[t] + b_out
// out_structure[n,t] = mean_k hidden
// One block (128 threads) per node; thread t owns channel t.
// ---------------------------------------------------------------------------
__global__ __launch_bounds__(128) void pgnn_gather_kernel(
    const float* __restrict__ dm,        // dists_max [N,16]
    const float* __restrict__ bh,        // b_hidden [128]
    const float* __restrict__ wo,        // w_out [128]
    const float* __restrict__ bo,        // b_out [1]
    float* __restrict__ out)             // [N*16 | N*128]
{
    const int n = blockIdx.x;
    const int t = threadIdx.x;
    const int warp = t >> 5, lane = t & 31;

    __shared__ float s_dm[KNN];
    __shared__ int   s_idx[KNN];
    __shared__ float s_part[KNN * 4];

    if (t < KNN) {
        s_dm[t]  = dm[(long long)n * KNN + t];
        s_idx[t] = g_idx[n * KNN + t];
    }
    __syncthreads();

    const float c = g_S[(long long)n * D + t] + bh[t];
    const float w = wo[t];
    float acc = 0.f;

    #pragma unroll
    for (int k = 0; k < KNN; k++) {
        float p = __ldg(&g_P[(long long)s_idx[k] * D + t]);
        float h = fmaxf(fmaf(s_dm[k], p, c), 0.f);
        acc += h;
        float pk = h * w;
        pk += __shfl_xor_sync(0xFFFFFFFFu, pk, 16);
        pk += __shfl_xor_sync(0xFFFFFFFFu, pk, 8);
        pk += __shfl_xor_sync(0xFFFFFFFFu, pk, 4);
        pk += __shfl_xor_sync(0xFFFFFFFFu, pk, 2);
        pk += __shfl_xor_sync(0xFFFFFFFFu, pk, 1);
        if (lane == 0) s_part[k * 4 + warp] = pk;
    }
    __syncthreads();

    if (t < KNN) {
        float v = s_part[t * 4] + s_part[t * 4 + 1] +
                  s_part[t * 4 + 2] + s_part[t * 4 + 3] + bo[0];
        out[(long long)n * KNN + t] = v;
    }
    out[(long long)N_NODES * KNN + (long long)n * D + t] = acc * (1.f / (float)KNN);
}

// ---------------------------------------------------------------------------
extern "C" void kernel_launch(void* const* d_in, const int* in_sizes, int n_in,
                              void* d_out, int out_size)
{
    const float* feature = (const float*)d_in[0];   // [N,128]
    const float* dmax    = (const float*)d_in[1];   // [N,16]
    const void*  dargm   = (const void*)d_in[2];    // [N,16] int32 or int64
    const float* W       = (const float*)d_in[3];   // [256,128]
    const float* bh      = (const float*)d_in[4];   // [128]
    const float* wo      = (const float*)d_in[5];   // [128,1]
    const float* bo      = (const float*)d_in[6];   // [1]
    float* out = (float*)d_out;

    // Index normalization (dtype-robust)
    pgnn_detect_idx_kernel<<<1, 32>>>((const unsigned long long*)dargm);
    pgnn_convert_idx_kernel<<<(N_NODES * KNN + 255) / 256, 256>>>(dargm);

    // Fused P|S GEMM
    size_t smem_bytes = (size_t)(128 * 256 + TILE_ROWS * D) * sizeof(float); // 160 KB
    cudaFuncSetAttribute(pgnn_gemm_kernel,
                         cudaFuncAttributeMaxDynamicSharedMemorySize,
                         (int)smem_bytes);
    int grid = (N_NODES + TILE_ROWS * CHUNKS - 1) / (TILE_ROWS * CHUNKS); // 391
    pgnn_gemm_kernel<<<grid, 256, smem_bytes>>>(feature, W);

    // Gather + epilogue
    pgnn_gather_kernel<<<N_NODES, 128>>>(dmax, bh, wo, bo, out);
}

// round 4
// speedup vs baseline: 1.7781x; 1.7781x over previous
#include <cuda_runtime.h>
#include <cuda_bf16.h>

#define N_NODES 100000
#define KNN 16
#define D 128

// Scratch (static device arrays — no allocation anywhere)
__device__ float g_P[(size_t)N_NODES * D];   // feature @ Wm
__device__ float g_S[(size_t)N_NODES * D];   // feature @ Ws
__device__ int   g_idx_is64;

// ---------------------------------------------------------------------------
// Index dtype detection: genuine int64 indices are all < N_NODES; an int32
// buffer viewed as int64 packs two indices and is ~never in range.
// Reads only 4KB — safe under both layouts.
// ---------------------------------------------------------------------------
__global__ void pgnn_detect_idx_kernel(const unsigned long long* __restrict__ buf)
{
    if (threadIdx.x == 0 && blockIdx.x == 0) {
        int bad = 0;
        for (int i = 0; i < 512; i++)
            if (buf[i] >= (unsigned long long)N_NODES) bad++;
        g_idx_is64 = (bad == 0) ? 1 : 0;
    }
}

// ---------------------------------------------------------------------------
// Kernel 1: fused GEMM  C[N,128] = feature[N,128] @ W_half
//   blockIdx.y = 0 -> Wm (W rows 0..127)   -> g_P
//   blockIdx.y = 1 -> Ws (W rows 128..255) -> g_S
// 256 threads/block, tile 64 rows x 128 cols, microtile 8x4 (float4 cols).
// Smem: W-half 64KB + A-tile 32KB = 96KB -> 2 CTAs/SM (16 warps).
// ---------------------------------------------------------------------------
#define TILE_ROWS 64
#define CHUNKS 4

extern __shared__ float smem_dyn[];

__global__ __launch_bounds__(256, 2) void pgnn_gemm_kernel(
    const float* __restrict__ A,   // feature [N,128]
    const float* __restrict__ W)   // W_hidden [256,128]
{
    float* Wsm = smem_dyn;              // [128][128]
    float* Asm = smem_dyn + 128 * 128;  // [64][128]

    const int tid  = threadIdx.x;
    const int warp = tid >> 5;
    const int lane = tid & 31;

    const float* Whalf = W + (size_t)blockIdx.y * 128 * 128;
    float* dst = blockIdx.y ? g_S : g_P;

    // ---- load W-half (16384 floats) ----
    #pragma unroll
    for (int i = 0; i < 16; i++) {
        int e = (i * 256 + tid) * 4;
        *(float4*)(Wsm + e) = *(const float4*)(Whalf + e);
    }

    for (int ch = 0; ch < CHUNKS; ch++) {
        long long base = ((long long)blockIdx.x * CHUNKS + ch) * TILE_ROWS;
        if (base >= N_NODES) break;
        const bool full = (base + TILE_ROWS <= N_NODES);
        __syncthreads();   // covers Wsm (first iter) + Asm reuse

        // ---- load A tile (64 x 128) ----
        if (full) {
            const float* src = A + base * D;
            #pragma unroll
            for (int i = 0; i < 8; i++) {
                int e = (i * 256 + tid) * 4;
                *(float4*)(Asm + e) = *(const float4*)(src + e);
            }
        } else {
            #pragma unroll
            for (int i = 0; i < 8; i++) {
                int e = (i * 256 + tid) * 4;
                int r = e >> 7, c = e & 127;
                long long grow = base + r;
                float4 v = make_float4(0.f, 0.f, 0.f, 0.f);
                if (grow < N_NODES) v = *(const float4*)(A + grow * D + c);
                *(float4*)(Asm + r * D + c) = v;
            }
        }
        __syncthreads();

        float4 acc[8];
        #pragma unroll
        for (int r = 0; r < 8; r++) acc[r] = make_float4(0.f, 0.f, 0.f, 0.f);

        const int colP = lane * 4;
        const int rowb = warp * 8;

        #pragma unroll 8
        for (int d = 0; d < D; d++) {
            float4 w0 = *(const float4*)(Wsm + d * 128 + colP);
            float a[8];
            #pragma unroll
            for (int r = 0; r < 8; r++) a[r] = Asm[(rowb + r) * D + d];  // broadcast
            #pragma unroll
            for (int r = 0; r < 8; r++) {
                acc[r].x = fmaf(a[r], w0.x, acc[r].x);
                acc[r].y = fmaf(a[r], w0.y, acc[r].y);
                acc[r].z = fmaf(a[r], w0.z, acc[r].z);
                acc[r].w = fmaf(a[r], w0.w, acc[r].w);
            }
        }

        #pragma unroll
        for (int r = 0; r < 8; r++) {
            long long grow = base + rowb + r;
            if (grow < N_NODES)
                *(float4*)(dst + grow * D + colP) = acc[r];
        }
    }
}

// ---------------------------------------------------------------------------
// Kernel 2: gather + relu + reductions. Warp-per-node, lane owns 4 channels.
// hidden[n,k,c] = relu(dm[n,k]*P[idx[n,k]][c] + S[n][c] + bh[c])
// out_position[n,k]  = sum_c hidden*wo[c] + bo
// out_structure[n,c] = mean_k hidden
// No shared memory, no __syncthreads. 8 nodes per 256-thread block.
// ---------------------------------------------------------------------------
__global__ __launch_bounds__(256) void pgnn_gather_kernel(
    const float* __restrict__ dm,        // dists_max [N,16]
    const void*  __restrict__ idxbuf,    // dists_argmax [N,16] (i32 or i64)
    const float* __restrict__ bh,        // b_hidden [128]
    const float* __restrict__ wo,        // w_out [128]
    const float* __restrict__ bo,        // b_out [1]
    float* __restrict__ out)             // [N*16 | N*128]
{
    const int warp = threadIdx.x >> 5;
    const int lane = threadIdx.x & 31;
    const int n = blockIdx.x * 8 + warp;
    if (n >= N_NODES) return;

    const int c4 = lane * 4;

    // lane k (k<16) holds idx[k], dm[k]
    int   my_idx = 0;
    float my_dm  = 0.f;
    if (lane < KNN) {
        long long v;
        if (g_idx_is64) v = ((const long long*)idxbuf)[(long long)n * KNN + lane];
        else            v = (long long)((const int*)idxbuf)[(long long)n * KNN + lane];
        if (v < 0) v = 0;
        if (v >= N_NODES) v = N_NODES - 1;
        my_idx = (int)v;
        my_dm  = dm[(long long)n * KNN + lane];
    }

    // per-lane constants
    float4 s4 = *(const float4*)(g_S + (long long)n * D + c4);
    float4 b4 = __ldg((const float4*)(bh + c4));
    float4 w4 = __ldg((const float4*)(wo + c4));
    float  bout = __ldg(bo);
    float4 cst = make_float4(s4.x + b4.x, s4.y + b4.y, s4.z + b4.z, s4.w + b4.w);

    float4 acc = make_float4(0.f, 0.f, 0.f, 0.f);
    float  posreg = 0.f;

    #pragma unroll
    for (int k = 0; k < KNN; k++) {
        int   j  = __shfl_sync(0xFFFFFFFFu, my_idx, k);
        float dk = __shfl_sync(0xFFFFFFFFu, my_dm, k);
        float4 p = __ldg((const float4*)(g_P + (long long)j * D + c4));

        float hx = fmaxf(fmaf(dk, p.x, cst.x), 0.f);
        float hy = fmaxf(fmaf(dk, p.y, cst.y), 0.f);
        float hz = fmaxf(fmaf(dk, p.z, cst.z), 0.f);
        float hw = fmaxf(fmaf(dk, p.w, cst.w), 0.f);

        acc.x += hx; acc.y += hy; acc.z += hz; acc.w += hw;

        float pk = fmaf(hx, w4.x, fmaf(hy, w4.y, fmaf(hz, w4.z, hw * w4.w)));
        pk += __shfl_xor_sync(0xFFFFFFFFu, pk, 16);
        pk += __shfl_xor_sync(0xFFFFFFFFu, pk, 8);
        pk += __shfl_xor_sync(0xFFFFFFFFu, pk, 4);
        pk += __shfl_xor_sync(0xFFFFFFFFu, pk, 2);
        pk += __shfl_xor_sync(0xFFFFFFFFu, pk, 1);
        if (lane == k) posreg = pk + bout;
    }

    // out_position: lanes 0..15 write 64B contiguous
    if (lane < KNN)
        out[(long long)n * KNN + lane] = posreg;

    // out_structure: one STG.128 per lane
    const float inv = 1.f / (float)KNN;
    float4 os = make_float4(acc.x * inv, acc.y * inv, acc.z * inv, acc.w * inv);
    *(float4*)(out + (long long)N_NODES * KNN + (long long)n * D + c4) = os;
}

// ---------------------------------------------------------------------------
extern "C" void kernel_launch(void* const* d_in, const int* in_sizes, int n_in,
                              void* d_out, int out_size)
{
    const float* feature = (const float*)d_in[0];   // [N,128]
    const float* dmax    = (const float*)d_in[1];   // [N,16]
    const void*  dargm   = (const void*)d_in[2];    // [N,16] i32/i64
    const float* W       = (const float*)d_in[3];   // [256,128]
    const float* bh      = (const float*)d_in[4];   // [128]
    const float* wo      = (const float*)d_in[5];   // [128,1]
    const float* bo      = (const float*)d_in[6];   // [1]
    float* out = (float*)d_out;

    pgnn_detect_idx_kernel<<<1, 32>>>((const unsigned long long*)dargm);

    size_t smem_bytes = (size_t)(128 * 128 + TILE_ROWS * D) * sizeof(float); // 96 KB
    cudaFuncSetAttribute(pgnn_gemm_kernel,
                         cudaFuncAttributeMaxDynamicSharedMemorySize,
                         (int)smem_bytes);
    dim3 grid((N_NODES + TILE_ROWS * CHUNKS - 1) / (TILE_ROWS * CHUNKS), 2); // 391 x 2
    pgnn_gemm_kernel<<<grid, 256, smem_bytes>>>(feature, W);

    pgnn_gather_kernel<<<(N_NODES + 7) / 8, 256>>>(dmax, dargm, bh, wo, bo, out);
}

// round 7
// speedup vs baseline: 1.8894x; 1.0626x over previous
#include <cuda_runtime.h>
#include <cuda_bf16.h>

#define N_NODES 100000
#define KNN 16
#define D 128

// Scratch (static device arrays — no allocation anywhere)
__device__ float g_P[(size_t)N_NODES * D];   // feature @ Wm
__device__ float g_S[(size_t)N_NODES * D];   // feature @ Ws
__device__ int   g_idx_is64;

// ---------------------------------------------------------------------------
// Kernel 1: fused GEMM  C[N,128] = feature[N,128] @ W_half
//   blockIdx.y = 0 -> Wm (W rows 0..127)   -> g_P
//   blockIdx.y = 1 -> Ws (W rows 128..255) -> g_S
// 256 threads/block, tile 64 rows x 128 cols, microtile 8x4 (float4 cols).
// Smem: W-half 64KB + A-tile 32KB = 96KB -> 2 CTAs/SM.
// Block (0,0) also performs idx-dtype detection (parallel, ~free):
// genuine int64 indices are all < N_NODES; an int32 buffer viewed as int64
// packs two indices and is ~never in range. Reads only 4KB (safe for both).
// ---------------------------------------------------------------------------
#define TILE_ROWS 64
#define CHUNKS 4

extern __shared__ float smem_dyn[];

__global__ __launch_bounds__(256, 2) void pgnn_gemm_kernel(
    const float* __restrict__ A,     // feature [N,128]
    const float* __restrict__ W,     // W_hidden [256,128]
    const unsigned long long* __restrict__ idx_u64)  // raw idx buffer
{
    float* Wsm = smem_dyn;              // [128][128]
    float* Asm = smem_dyn + 128 * 128;  // [64][128]

    const int tid  = threadIdx.x;
    const int warp = tid >> 5;
    const int lane = tid & 31;

    // ---- dtype detection, folded into block (0,0) ----
    if (blockIdx.x == 0 && blockIdx.y == 0) {
        unsigned long long v0 = idx_u64[tid * 2];
        unsigned long long v1 = idx_u64[tid * 2 + 1];
        int ok = (v0 < (unsigned long long)N_NODES) &&
                 (v1 < (unsigned long long)N_NODES);
        int all_ok = __syncthreads_and(ok);
        if (tid == 0) g_idx_is64 = all_ok ? 1 : 0;
    }

    const float* Whalf = W + (size_t)blockIdx.y * 128 * 128;
    float* dst = blockIdx.y ? g_S : g_P;

    // ---- load W-half (16384 floats) ----
    #pragma unroll
    for (int i = 0; i < 16; i++) {
        int e = (i * 256 + tid) * 4;
        *(float4*)(Wsm + e) = *(const float4*)(Whalf + e);
    }

    for (int ch = 0; ch < CHUNKS; ch++) {
        long long base = ((long long)blockIdx.x * CHUNKS + ch) * TILE_ROWS;
        if (base >= N_NODES) break;
        const bool full = (base + TILE_ROWS <= N_NODES);
        __syncthreads();   // covers Wsm (first iter) + Asm reuse

        // ---- load A tile (64 x 128) ----
        if (full) {
            const float* src = A + base * D;
            #pragma unroll
            for (int i = 0; i < 8; i++) {
                int e = (i * 256 + tid) * 4;
                *(float4*)(Asm + e) = *(const float4*)(src + e);
            }
        } else {
            #pragma unroll
            for (int i = 0; i < 8; i++) {
                int e = (i * 256 + tid) * 4;
                int r = e >> 7, c = e & 127;
                long long grow = base + r;
                float4 v = make_float4(0.f, 0.f, 0.f, 0.f);
                if (grow < N_NODES) v = *(const float4*)(A + grow * D + c);
                *(float4*)(Asm + r * D + c) = v;
            }
        }
        __syncthreads();

        float4 acc[8];
        #pragma unroll
        for (int r = 0; r < 8; r++) acc[r] = make_float4(0.f, 0.f, 0.f, 0.f);

        const int colP = lane * 4;
        const int rowb = warp * 8;

        // d-steps of 4: 12 LDS.128 per 128 FFMA (vs 36 per 128 before)
        #pragma unroll 4
        for (int d0 = 0; d0 < D; d0 += 4) {
            float4 w0 = *(const float4*)(Wsm + (d0 + 0) * 128 + colP);
            float4 w1 = *(const float4*)(Wsm + (d0 + 1) * 128 + colP);
            float4 w2 = *(const float4*)(Wsm + (d0 + 2) * 128 + colP);
            float4 w3 = *(const float4*)(Wsm + (d0 + 3) * 128 + colP);
            #pragma unroll
            for (int r = 0; r < 8; r++) {
                float4 a = *(const float4*)(Asm + (rowb + r) * D + d0); // broadcast
                acc[r].x = fmaf(a.x, w0.x, acc[r].x);
                acc[r].y = fmaf(a.x, w0.y, acc[r].y);
                acc[r].z = fmaf(a.x, w0.z, acc[r].z);
                acc[r].w = fmaf(a.x, w0.w, acc[r].w);
                acc[r].x = fmaf(a.y, w1.x, acc[r].x);
                acc[r].y = fmaf(a.y, w1.y, acc[r].y);
                acc[r].z = fmaf(a.y, w1.z, acc[r].z);
                acc[r].w = fmaf(a.y, w1.w, acc[r].w);
                acc[r].x = fmaf(a.z, w2.x, acc[r].x);
                acc[r].y = fmaf(a.z, w2.y, acc[r].y);
                acc[r].z = fmaf(a.z, w2.z, acc[r].z);
                acc[r].w = fmaf(a.z, w2.w, acc[r].w);
                acc[r].x = fmaf(a.w, w3.x, acc[r].x);
                acc[r].y = fmaf(a.w, w3.y, acc[r].y);
                acc[r].z = fmaf(a.w, w3.z, acc[r].z);
                acc[r].w = fmaf(a.w, w3.w, acc[r].w);
            }
        }

        #pragma unroll
        for (int r = 0; r < 8; r++) {
            long long grow = base + rowb + r;
            if (grow < N_NODES)
                *(float4*)(dst + grow * D + colP) = acc[r];
        }
    }
}

// ---------------------------------------------------------------------------
// Kernel 2: gather + relu + reductions. Warp-per-node, lane owns 4 channels.
// Gathers issued in batches of 8 LDG.128 before the compute/reduce phase,
// so load latency overlaps the butterfly shfl chain.
// ---------------------------------------------------------------------------
__global__ __launch_bounds__(256) void pgnn_gather_kernel(
    const float* __restrict__ dm,        // dists_max [N,16]
    const void*  __restrict__ idxbuf,    // dists_argmax [N,16] (i32 or i64)
    const float* __restrict__ bh,        // b_hidden [128]
    const float* __restrict__ wo,        // w_out [128]
    const float* __restrict__ bo,        // b_out [1]
    float* __restrict__ out)             // [N*16 | N*128]
{
    const int warp = threadIdx.x >> 5;
    const int lane = threadIdx.x & 31;
    const int n = blockIdx.x * 8 + warp;
    if (n >= N_NODES) return;

    const int c4 = lane * 4;

    // lane k (k<16) holds idx[k], dm[k]
    int   my_idx = 0;
    float my_dm  = 0.f;
    if (lane < KNN) {
        long long v;
        if (g_idx_is64) v = ((const long long*)idxbuf)[(long long)n * KNN + lane];
        else            v = (long long)((const int*)idxbuf)[(long long)n * KNN + lane];
        if (v < 0) v = 0;
        if (v >= N_NODES) v = N_NODES - 1;
        my_idx = (int)v;
        my_dm  = dm[(long long)n * KNN + lane];
    }

    // per-lane constants
    float4 s4 = *(const float4*)(g_S + (long long)n * D + c4);
    float4 b4 = __ldg((const float4*)(bh + c4));
    float4 w4 = __ldg((const float4*)(wo + c4));
    float  bout = __ldg(bo);
    float4 cst = make_float4(s4.x + b4.x, s4.y + b4.y, s4.z + b4.z, s4.w + b4.w);

    float4 acc = make_float4(0.f, 0.f, 0.f, 0.f);
    float  posreg = 0.f;

    #pragma unroll
    for (int h = 0; h < 2; h++) {
        // batch of 8 gathers
        float4 p[8];
        #pragma unroll
        for (int k = 0; k < 8; k++) {
            int j = __shfl_sync(0xFFFFFFFFu, my_idx, h * 8 + k);
            p[k] = __ldg((const float4*)(g_P + (long long)j * D + c4));
        }
        // compute + reduce
        #pragma unroll
        for (int k = 0; k < 8; k++) {
            int   kk = h * 8 + k;
            float dk = __shfl_sync(0xFFFFFFFFu, my_dm, kk);

            float hx = fmaxf(fmaf(dk, p[k].x, cst.x), 0.f);
            float hy = fmaxf(fmaf(dk, p[k].y, cst.y), 0.f);
            float hz = fmaxf(fmaf(dk, p[k].z, cst.z), 0.f);
            float hw = fmaxf(fmaf(dk, p[k].w, cst.w), 0.f);

            acc.x += hx; acc.y += hy; acc.z += hz; acc.w += hw;

            float pk = fmaf(hx, w4.x, fmaf(hy, w4.y, fmaf(hz, w4.z, hw * w4.w)));
            pk += __shfl_xor_sync(0xFFFFFFFFu, pk, 16);
            pk += __shfl_xor_sync(0xFFFFFFFFu, pk, 8);
            pk += __shfl_xor_sync(0xFFFFFFFFu, pk, 4);
            pk += __shfl_xor_sync(0xFFFFFFFFu, pk, 2);
            pk += __shfl_xor_sync(0xFFFFFFFFu, pk, 1);
            if (lane == kk) posreg = pk + bout;
        }
    }

    // out_position: lanes 0..15 write 64B contiguous
    if (lane < KNN)
        out[(long long)n * KNN + lane] = posreg;

    // out_structure: one STG.128 per lane
    const float inv = 1.f / (float)KNN;
    float4 os = make_float4(acc.x * inv, acc.y * inv, acc.z * inv, acc.w * inv);
    *(float4*)(out + (long long)N_NODES * KNN + (long long)n * D + c4) = os;
}

// ---------------------------------------------------------------------------
extern "C" void kernel_launch(void* const* d_in, const int* in_sizes, int n_in,
                              void* d_out, int out_size)
{
    const float* feature = (const float*)d_in[0];   // [N,128]
    const float* dmax    = (const float*)d_in[1];   // [N,16]
    const void*  dargm   = (const void*)d_in[2];    // [N,16] i32/i64
    const float* W       = (const float*)d_in[3];   // [256,128]
    const float* bh      = (const float*)d_in[4];   // [128]
    const float* wo      = (const float*)d_in[5];   // [128,1]
    const float* bo      = (const float*)d_in[6];   // [1]
    float* out = (float*)d_out;

    size_t smem_bytes = (size_t)(128 * 128 + TILE_ROWS * D) * sizeof(float); // 96 KB
    cudaFuncSetAttribute(pgnn_gemm_kernel,
                         cudaFuncAttributeMaxDynamicSharedMemorySize,
                         (int)smem_bytes);
    dim3 grid((N_NODES + TILE_ROWS * CHUNKS - 1) / (TILE_ROWS * CHUNKS), 2); // 391 x 2
    pgnn_gemm_kernel<<<grid, 256, smem_bytes>>>(feature, W,
                                                (const unsigned long long*)dargm);

    pgnn_gather_kernel<<<(N_NODES + 7) / 8, 256>>>(dmax, dargm, bh, wo, bo, out);
}

// round 10
// speedup vs baseline: 2.0646x; 1.0927x over previous
#include <cuda_runtime.h>
#include <cuda_bf16.h>

#define N_NODES 100000
#define KNN 16
#define D 128

// Scratch (static device arrays — no allocation anywhere)
__device__ float g_P[(size_t)N_NODES * D];   // feature @ Wm
__device__ float g_S[(size_t)N_NODES * D];   // feature @ Ws
__device__ int   g_idx_is64;

// ---------------------------------------------------------------------------
// helpers
// ---------------------------------------------------------------------------
__device__ __forceinline__ unsigned f2tf(float x) {
    unsigned r;
    asm("cvt.rna.tf32.f32 %0, %1;" : "=r"(r) : "f"(x));
    return r;
}

__device__ __forceinline__ void mma_tf32(float c[4],
                                         unsigned a0, unsigned a1,
                                         unsigned a2, unsigned a3,
                                         unsigned b0, unsigned b1) {
    asm volatile(
        "mma.sync.aligned.m16n8k8.row.col.f32.tf32.tf32.f32 "
        "{%0,%1,%2,%3}, {%4,%5,%6,%7}, {%8,%9}, {%0,%1,%2,%3};"
        : "+f"(c[0]), "+f"(c[1]), "+f"(c[2]), "+f"(c[3])
        : "r"(a0), "r"(a1), "r"(a2), "r"(a3), "r"(b0), "r"(b1));
}

// ---------------------------------------------------------------------------
// Kernel 1: 3xTF32 tensor-core GEMM  C[N,128] = feature[N,128] @ W_half
//   blockIdx.y = 0 -> Wm -> g_P ; blockIdx.y = 1 -> Ws -> g_S
// Block tile 64 rows x 128 cols; 8 warps as 2(m) x 4(n); warp tile 32x32.
// mma.sync.m16n8k8.tf32 with hi/lo error compensation:
//   C = ah*bh + al*bh + ah*bl   (~fp32 accuracy)
// Smem: Wsm [128][136] fp32 (69.6KB, B-frag loads conflict-free),
//       Asm [64][136] fp32 (34.8KB). Total ~104.5KB -> 2 CTAs/SM.
// Block (0,0) also does idx dtype detection (parallel 4KB read):
// genuine int64 indices are all < N_NODES; int32 viewed as int64 is not.
// ---------------------------------------------------------------------------
#define BROWS 64
#define WSTRIDE 136

extern __shared__ float smem_dyn[];

__global__ __launch_bounds__(256, 2) void pgnn_gemm_kernel(
    const float* __restrict__ A,     // feature [N,128]
    const float* __restrict__ W,     // W_hidden [256,128]
    const unsigned long long* __restrict__ idx_u64)
{
    float* Wsm = smem_dyn;                   // [128][136]
    float* Asm = smem_dyn + 128 * WSTRIDE;   // [64][136]

    const int tid  = threadIdx.x;
    const int wid  = tid >> 5;
    const int lane = tid & 31;
    const int q    = lane >> 2;   // groupID 0..7
    const int s    = lane & 3;    // threadID_in_group 0..3

    // ---- dtype detection, folded into block (0,0) ----
    if (blockIdx.x == 0 && blockIdx.y == 0) {
        unsigned long long v0 = idx_u64[tid * 2];
        unsigned long long v1 = idx_u64[tid * 2 + 1];
        int ok = (v0 < (unsigned long long)N_NODES) &&
                 (v1 < (unsigned long long)N_NODES);
        int all_ok = __syncthreads_and(ok);
        if (tid == 0) g_idx_is64 = all_ok ? 1 : 0;
    }

    const float* Whalf = W + (size_t)blockIdx.y * 128 * 128;
    float* dst = blockIdx.y ? g_S : g_P;
    const long long base = (long long)blockIdx.x * BROWS;

    // ---- load W half [128][128] into Wsm (row d, col o) ----
    #pragma unroll
    for (int i = 0; i < 16; i++) {
        int e  = i * 256 + tid;          // float4 index, 0..4095
        int d  = e >> 5;
        int o4 = (e & 31) * 4;
        float4 v = *(const float4*)(Whalf + d * 128 + o4);
        *(float4*)(Wsm + d * WSTRIDE + o4) = v;
    }

    // ---- load A tile [64][128] into Asm ----
    #pragma unroll
    for (int i = 0; i < 8; i++) {
        int e  = i * 256 + tid;          // float4 index, 0..2047
        int r  = e >> 5;
        int c4 = (e & 31) * 4;
        long long grow = base + r;
        float4 v = make_float4(0.f, 0.f, 0.f, 0.f);
        if (grow < N_NODES) v = *(const float4*)(A + grow * D + c4);
        *(float4*)(Asm + r * WSTRIDE + c4) = v;
    }
    __syncthreads();

    const int warp_m = wid >> 2;  // 0..1
    const int warp_n = wid & 3;   // 0..3
    const int rbase  = warp_m * 32;
    const int cbase  = warp_n * 32;

    float acc[2][4][4];
    #pragma unroll
    for (int t = 0; t < 2; t++)
        #pragma unroll
        for (int j = 0; j < 4; j++)
            #pragma unroll
            for (int i = 0; i < 4; i++) acc[t][j][i] = 0.f;

    #pragma unroll 2
    for (int kc = 0; kc < 16; kc++) {
        const int k0 = kc * 8;

        // ---- A fragments for 2 m-tiles, with tf32 hi/lo split ----
        unsigned ah[2][4], al[2][4];
        #pragma unroll
        for (int t = 0; t < 2; t++) {
            int r0 = rbase + t * 16 + q;
            float a0 = Asm[(r0)     * WSTRIDE + k0 + s];
            float a1 = Asm[(r0 + 8) * WSTRIDE + k0 + s];
            float a2 = Asm[(r0)     * WSTRIDE + k0 + 4 + s];
            float a3 = Asm[(r0 + 8) * WSTRIDE + k0 + 4 + s];
            ah[t][0] = f2tf(a0); al[t][0] = f2tf(a0 - __uint_as_float(ah[t][0]));
            ah[t][1] = f2tf(a1); al[t][1] = f2tf(a1 - __uint_as_float(ah[t][1]));
            ah[t][2] = f2tf(a2); al[t][2] = f2tf(a2 - __uint_as_float(ah[t][2]));
            ah[t][3] = f2tf(a3); al[t][3] = f2tf(a3 - __uint_as_float(ah[t][3]));
        }

        // ---- 4 n-tiles: B fragments + 3-term mma ----
        #pragma unroll
        for (int j = 0; j < 4; j++) {
            int col = cbase + j * 8 + q;
            float b0 = Wsm[(k0 + s)     * WSTRIDE + col];
            float b1 = Wsm[(k0 + 4 + s) * WSTRIDE + col];
            unsigned bh0 = f2tf(b0), bh1 = f2tf(b1);
            unsigned bl0 = f2tf(b0 - __uint_as_float(bh0));
            unsigned bl1 = f2tf(b1 - __uint_as_float(bh1));
            #pragma unroll
            for (int t = 0; t < 2; t++) {
                mma_tf32(acc[t][j], ah[t][0], ah[t][1], ah[t][2], ah[t][3], bh0, bh1);
                mma_tf32(acc[t][j], al[t][0], al[t][1], al[t][2], al[t][3], bh0, bh1);
                mma_tf32(acc[t][j], ah[t][0], ah[t][1], ah[t][2], ah[t][3], bl0, bl1);
            }
        }
    }

    // ---- epilogue: float2 stores ----
    #pragma unroll
    for (int t = 0; t < 2; t++) {
        long long row0 = base + rbase + t * 16 + q;
        long long row8 = row0 + 8;
        #pragma unroll
        for (int j = 0; j < 4; j++) {
            int col = cbase + j * 8 + s * 2;
            if (row0 < N_NODES)
                *(float2*)(dst + row0 * D + col) =
                    make_float2(acc[t][j][0], acc[t][j][1]);
            if (row8 < N_NODES)
                *(float2*)(dst + row8 * D + col) =
                    make_float2(acc[t][j][2], acc[t][j][3]);
        }
    }
}

// ---------------------------------------------------------------------------
// Kernel 2: gather + relu + reductions. Warp-per-node, lane owns 4 channels.
// Gathers issued in batches of 8 LDG.128 before the compute/reduce phase.
// ---------------------------------------------------------------------------
__global__ __launch_bounds__(256) void pgnn_gather_kernel(
    const float* __restrict__ dm,        // dists_max [N,16]
    const void*  __restrict__ idxbuf,    // dists_argmax [N,16] (i32 or i64)
    const float* __restrict__ bh,        // b_hidden [128]
    const float* __restrict__ wo,        // w_out [128]
    const float* __restrict__ bo,        // b_out [1]
    float* __restrict__ out)             // [N*16 | N*128]
{
    const int warp = threadIdx.x >> 5;
    const int lane = threadIdx.x & 31;
    const int n = blockIdx.x * 8 + warp;
    if (n >= N_NODES) return;

    const int c4 = lane * 4;

    int   my_idx = 0;
    float my_dm  = 0.f;
    if (lane < KNN) {
        long long v;
        if (g_idx_is64) v = ((const long long*)idxbuf)[(long long)n * KNN + lane];
        else            v = (long long)((const int*)idxbuf)[(long long)n * KNN + lane];
        if (v < 0) v = 0;
        if (v >= N_NODES) v = N_NODES - 1;
        my_idx = (int)v;
        my_dm  = dm[(long long)n * KNN + lane];
    }

    float4 s4 = *(const float4*)(g_S + (long long)n * D + c4);
    float4 b4 = __ldg((const float4*)(bh + c4));
    float4 w4 = __ldg((const float4*)(wo + c4));
    float  bout = __ldg(bo);
    float4 cst = make_float4(s4.x + b4.x, s4.y + b4.y, s4.z + b4.z, s4.w + b4.w);

    float4 acc = make_float4(0.f, 0.f, 0.f, 0.f);
    float  posreg = 0.f;

    #pragma unroll
    for (int h = 0; h < 2; h++) {
        float4 p[8];
        #pragma unroll
        for (int k = 0; k < 8; k++) {
            int j = __shfl_sync(0xFFFFFFFFu, my_idx, h * 8 + k);
            p[k] = __ldg((const float4*)(g_P + (long long)j * D + c4));
        }
        #pragma unroll
        for (int k = 0; k < 8; k++) {
            int   kk = h * 8 + k;
            float dk = __shfl_sync(0xFFFFFFFFu, my_dm, kk);

            float hx = fmaxf(fmaf(dk, p[k].x, cst.x), 0.f);
            float hy = fmaxf(fmaf(dk, p[k].y, cst.y), 0.f);
            float hz = fmaxf(fmaf(dk, p[k].z, cst.z), 0.f);
            float hw = fmaxf(fmaf(dk, p[k].w, cst.w), 0.f);

            acc.x += hx; acc.y += hy; acc.z += hz; acc.w += hw;

            float pk = fmaf(hx, w4.x, fmaf(hy, w4.y, fmaf(hz, w4.z, hw * w4.w)));
            pk += __shfl_xor_sync(0xFFFFFFFFu, pk, 16);
            pk += __shfl_xor_sync(0xFFFFFFFFu, pk, 8);
            pk += __shfl_xor_sync(0xFFFFFFFFu, pk, 4);
            pk += __shfl_xor_sync(0xFFFFFFFFu, pk, 2);
            pk += __shfl_xor_sync(0xFFFFFFFFu, pk, 1);
            if (lane == kk) posreg = pk + bout;
        }
    }

    if (lane < KNN)
        out[(long long)n * KNN + lane] = posreg;

    const float inv = 1.f / (float)KNN;
    float4 os = make_float4(acc.x * inv, acc.y * inv, acc.z * inv, acc.w * inv);
    *(float4*)(out + (long long)N_NODES * KNN + (long long)n * D + c4) = os;
}

// ---------------------------------------------------------------------------
extern "C" void kernel_launch(void* const* d_in, const int* in_sizes, int n_in,
                              void* d_out, int out_size)
{
    const float* feature = (const float*)d_in[0];   // [N,128]
    const float* dmax    = (const float*)d_in[1];   // [N,16]
    const void*  dargm   = (const void*)d_in[2];    // [N,16] i32/i64
    const float* W       = (const float*)d_in[3];   // [256,128]
    const float* bh      = (const float*)d_in[4];   // [128]
    const float* wo      = (const float*)d_in[5];   // [128,1]
    const float* bo      = (const float*)d_in[6];   // [1]
    float* out = (float*)d_out;

    size_t smem_bytes = (size_t)(128 * WSTRIDE + BROWS * WSTRIDE) * sizeof(float); // ~104.5 KB
    cudaFuncSetAttribute(pgnn_gemm_kernel,
                         cudaFuncAttributeMaxDynamicSharedMemorySize,
                         (int)smem_bytes);
    dim3 grid((N_NODES + BROWS - 1) / BROWS, 2);   // 1563 x 2
    pgnn_gemm_kernel<<<grid, 256, smem_bytes>>>(feature, W,
                                                (const unsigned long long*)dargm);

    pgnn_gather_kernel<<<(N_NODES + 7) / 8, 256>>>(dmax, dargm, bh, wo, bo, out);
}